// round 13
// baseline (speedup 1.0000x reference)
#include <cuda_runtime.h>
#include <cuda_fp16.h>
#include <cuda_bf16.h>
#include <math.h>
#include <stdint.h>

// Problem dims
#define B_   128
#define S_   196
#define K_   512
#define TCAP 16
#define TOUT 15
#define V_   32000
#define E_   512
#define H_   512

// ---------------- scratch (device globals; allocation-free) ----------------
__device__ float g_gix[TOUT * B_ * 3 * H_];        // x_t @ Wx^T  (t*128+b, 1536)
__device__ float g_h[(TOUT + 1) * B_ * H_];        // h_0..h_15 fp32 master
__device__ float g_qgh[B_ * 2048];                 // per-step [q | gh]
__device__ float g_gi[B_ * 3 * H_];
__device__ float g_bcat[2048];                     // [0 ; gru_bhh]
__device__ float g_bias2[1536];                    // Wih_ctx@fc0_b + b_ih
__device__ float g_fc0wT[512 * 512];

// fp16 operands
__device__ __half g_xe_h[TOUT * B_ * E_];
__device__ __half g_x_h[TOUT * B_ * H_];
__device__ __half g_fc1w_h[H_ * E_];
__device__ __half g_wk_h[H_ * K_];
__device__ __half g_feat_h[(size_t)B_ * S_ * K_];
__device__ __half g_keys_h[(size_t)B_ * S_ * H_];
__device__ __half g_wihx_h[1536 * 512];
__device__ __half g_wihc_h[1536 * 512];
__device__ __half g_fc0wT_h[512 * 512];
__device__ __half g_fc2w_h[(size_t)V_ * H_];
__device__ __half g_h16[(TOUT + 1) * B_ * H_];     // fp16 h, slot 0 = zeros
__device__ __half g_ctx_h[B_ * K_];
__device__ __half g_wcat_h[2048 * 512];            // [att_wq ; gru_whh] fp16
__device__ __half g_wprime_h[1536 * 512];

// grid-barrier state (zero-initialized): 8 striped counters, 256B apart
__device__ unsigned g_bar_cnt[8 * 64];
__device__ volatile unsigned g_bar_gen;

// ---------------- fast math helpers ----------------------------------------
__device__ __forceinline__ float tanh_fast(float x) {
    float y;
    asm("tanh.approx.f32 %0, %1;" : "=f"(y) : "f"(x));
    return y;
}

// ========================= mma helpers =====================================
__device__ __forceinline__ void ldsm4(uint32_t* r, uint32_t addr) {
    asm volatile("ldmatrix.sync.aligned.m8n8.x4.shared.b16 {%0,%1,%2,%3}, [%4];"
        : "=r"(r[0]), "=r"(r[1]), "=r"(r[2]), "=r"(r[3]) : "r"(addr));
}
__device__ __forceinline__ void mma16816(float* c, const uint32_t* a, const uint32_t* b) {
    asm volatile("mma.sync.aligned.m16n8k16.row.col.f32.f16.f16.f32 "
        "{%0,%1,%2,%3}, {%4,%5,%6,%7}, {%8,%9}, {%0,%1,%2,%3};"
        : "+f"(c[0]), "+f"(c[1]), "+f"(c[2]), "+f"(c[3])
        : "r"(a[0]), "r"(a[1]), "r"(a[2]), "r"(a[3]), "r"(b[0]), "r"(b[1]));
}
__device__ __forceinline__ void cpasync16(uint32_t dst, const void* src) {
    asm volatile("cp.async.cg.shared.global [%0], [%1], 16;" :: "r"(dst), "l"(src));
}

// ============ fp16 HMMA NT GEMM, 3-stage cp.async pipeline (R7 config) =====
// C[M,N] = A[M,K]h * B[N,K]h^T ; BM=BN=128, BK=64, 256 thr, 8 warps (2m x 4n)
// Dynamic smem: 3 stages x (A 16KB + B 16KB) = 96KB. XOR-swizzled 128B rows.
// modes: 0 plain f32, 3 +bias remap (m=t*128+b -> row b*15+t),
//        4 +bias store fp16, 5 plain store fp16
#define HG_SMEM (3 * 32768)

__global__ __launch_bounds__(256) void hgemm_nt(
    const __half* __restrict__ A, int lda,
    const __half* __restrict__ B, int ldb,
    void* __restrict__ Cv, int ldc, int K,
    const float* __restrict__ bias, int mode)
{
    extern __shared__ __half sm[];
    uint32_t sb = (uint32_t)__cvta_generic_to_shared(sm);
    const int tid = threadIdx.x, lane = tid & 31, warp = tid >> 5;
    const int wm = warp & 1, wn = warp >> 1;
    const int bn = blockIdx.x, bm = blockIdx.y;

    const __half* Abase = A + (size_t)(bm * 128) * lda;
    const __half* Bbase = B + (size_t)(bn * 128) * ldb;

    auto load_tile = [&](int kt, int st) {
        uint32_t abase_s = sb + st * 32768;
        uint32_t bbase_s = abase_s + 16384;
#pragma unroll
        for (int i = 0; i < 4; ++i) {
            int cid = i * 256 + tid;
            int row = cid >> 3, c8 = cid & 7;
            uint32_t soff = row * 128 + ((c8 * 16) ^ ((row & 7) * 16));
            cpasync16(abase_s + soff, Abase + (size_t)row * lda + kt * 64 + c8 * 8);
            cpasync16(bbase_s + soff, Bbase + (size_t)row * ldb + kt * 64 + c8 * 8);
        }
        asm volatile("cp.async.commit_group;" ::: "memory");
    };

    float acc[4][4][4] = {};
    const int a_r = ((lane >> 3) & 1) * 8 + (lane & 7);
    const int a_c = (lane >> 4) * 8;
    const int b_r = ((lane >> 4) & 1) * 8 + (lane & 7);
    const int b_c = ((lane >> 3) & 1) * 8;

    const int nkt = K / 64;
    load_tile(0, 0);
    if (nkt > 1) load_tile(1, 1);

    for (int kt = 0; kt < nkt; ++kt) {
        int st = kt % 3;
        if (kt + 1 < nkt) {
            asm volatile("cp.async.wait_group 1;" ::: "memory");
        } else {
            asm volatile("cp.async.wait_group 0;" ::: "memory");
        }
        __syncthreads();
        if (kt + 2 < nkt) load_tile(kt + 2, (kt + 2) % 3);

        uint32_t abase_s = sb + st * 32768;
        uint32_t bbase_s = abase_s + 16384;
#pragma unroll
        for (int ks = 0; ks < 4; ++ks) {
            int k = ks * 16;
            uint32_t af[4][4], bf[4][2];
#pragma unroll
            for (int mi = 0; mi < 4; ++mi) {
                int row = wm * 64 + mi * 16 + a_r;
                uint32_t addr = abase_s + row * 128 +
                                (((k + a_c) * 2) ^ ((row & 7) * 16));
                ldsm4(af[mi], addr);
            }
#pragma unroll
            for (int nh = 0; nh < 2; ++nh) {
                int row = wn * 32 + nh * 16 + b_r;
                uint32_t addr = bbase_s + row * 128 +
                                (((k + b_c) * 2) ^ ((row & 7) * 16));
                uint32_t r[4];
                ldsm4(r, addr);
                bf[2 * nh + 0][0] = r[0]; bf[2 * nh + 0][1] = r[1];
                bf[2 * nh + 1][0] = r[2]; bf[2 * nh + 1][1] = r[3];
            }
#pragma unroll
            for (int mi = 0; mi < 4; ++mi)
#pragma unroll
                for (int ni = 0; ni < 4; ++ni)
                    mma16816(acc[mi][ni], af[mi], bf[ni]);
        }
    }

    const int mb = bm * 128 + wm * 64;
    const int nb = bn * 128 + wn * 32;
    const int qr = lane >> 2, qc = (lane & 3) * 2;
#pragma unroll
    for (int mi = 0; mi < 4; ++mi) {
#pragma unroll
        for (int ni = 0; ni < 4; ++ni) {
            int n = nb + ni * 8 + qc;
            float bv = 0.f, bv2 = 0.f;
            if (mode == 3 || mode == 4) { bv = bias[n]; bv2 = bias[n + 1]; }
            float* c4 = acc[mi][ni];
#pragma unroll
            for (int half_ = 0; half_ < 2; ++half_) {
                int m = mb + mi * 16 + qr + half_ * 8;
                float v0 = c4[half_ * 2 + 0] + bv;
                float v1 = c4[half_ * 2 + 1] + bv2;
                if (mode == 4 || mode == 5) {
                    __half* C = (__half*)Cv;
                    *(__half2*)&C[(size_t)m * ldc + n] =
                        __halves2half2(__float2half(v0), __float2half(v1));
                } else if (mode == 3) {
                    int b = m & 127, t = m >> 7;
                    float* C = (float*)Cv;
                    *(float2*)&C[((size_t)b * TOUT + t) * ldc + n] = make_float2(v0, v1);
                } else {
                    float* C = (float*)Cv;
                    *(float2*)&C[(size_t)m * ldc + n] = make_float2(v0, v1);
                }
            }
        }
    }
}

// ====================== persistent recurrence kernel ========================
// grid = 128 CTAs x 256 thr (all resident). Striped-counter grid barrier.
// Dynamic smem 73728B: gemm 3 stages x (A 16KB + B 8KB); attention aliases it.

#define RC_SMEM 73728

__device__ __forceinline__ void grid_sync() {
    __syncthreads();
    if (threadIdx.x == 0) {
        __threadfence();
        unsigned gen = g_bar_gen;
        atomicAdd(&g_bar_cnt[(blockIdx.x & 7) * 64], 1u);
        if (blockIdx.x == 0) {
            unsigned sum;
            do {
                sum = 0;
#pragma unroll
                for (int i = 0; i < 8; ++i)
                    sum += *(volatile unsigned*)&g_bar_cnt[i * 64];
            } while (sum < gridDim.x);
#pragma unroll
            for (int i = 0; i < 8; ++i)
                *(volatile unsigned*)&g_bar_cnt[i * 64] = 0;
            __threadfence();
            g_bar_gen = gen + 1;
        } else {
            while (g_bar_gen == gen) { }
        }
        __threadfence();
    }
    __syncthreads();
}

// 64-col GEMM tile with cp.async pipeline + register double-buffered frags:
// C[128, 64 cols at tile bn] = A[128,512]h * B[bn-rows,512]h^T (+bias,+Add)
// 3 stages x (A 128x64h = 16KB, B 64x64h = 8KB). Same K/mma order as before.
__device__ void gemm_tile64_cp(
    const __half* __restrict__ A,
    const __half* __restrict__ B, int ldb,
    float* __restrict__ C, int ldc,
    const float* __restrict__ bias,
    const float* __restrict__ Add, int ldadd, int mode, int bn,
    char* dsm)
{
    uint32_t sb = (uint32_t)__cvta_generic_to_shared(dsm);
    int tid = threadIdx.x, lane = tid & 31, warp = tid >> 5;
    int wm = warp >> 1, wn = warp & 1;

    const __half* Bbase = B + (size_t)(bn * 64) * ldb;

    auto load_tile = [&](int kt, int st) {
        uint32_t abase_s = sb + st * 24576;
        uint32_t bbase_s = abase_s + 16384;
#pragma unroll
        for (int i = 0; i < 4; ++i) {               // A: 1024 16B chunks
            int cid = i * 256 + tid;
            int row = cid >> 3, c8 = cid & 7;
            uint32_t soff = row * 128 + ((c8 * 16) ^ ((row & 7) * 16));
            cpasync16(abase_s + soff, A + (size_t)row * 512 + kt * 64 + c8 * 8);
        }
#pragma unroll
        for (int i = 0; i < 2; ++i) {               // B: 512 16B chunks
            int cid = i * 256 + tid;
            int row = cid >> 3, c8 = cid & 7;
            uint32_t soff = row * 128 + ((c8 * 16) ^ ((row & 7) * 16));
            cpasync16(bbase_s + soff, Bbase + (size_t)row * ldb + kt * 64 + c8 * 8);
        }
        asm volatile("cp.async.commit_group;" ::: "memory");
    };

    float acc[2][4][4] = {};
    int a_r = ((lane >> 3) & 1) * 8 + (lane & 7);
    int a_c = (lane >> 4) * 8;
    int b_r = ((lane >> 4) & 1) * 8 + (lane & 7);
    int b_c = ((lane >> 3) & 1) * 8;

    load_tile(0, 0);
    load_tile(1, 1);

    for (int kt = 0; kt < 8; ++kt) {
        int st = kt % 3;
        if (kt + 1 < 8) {
            asm volatile("cp.async.wait_group 1;" ::: "memory");
        } else {
            asm volatile("cp.async.wait_group 0;" ::: "memory");
        }
        __syncthreads();
        if (kt + 2 < 8) load_tile(kt + 2, (kt + 2) % 3);

        uint32_t abase_s = sb + st * 24576;
        uint32_t bbase_s = abase_s + 16384;

        // fragment loader for one ks (k = ks*16 halves)
        uint32_t af[2][2][4], bf[2][4][2];
        auto load_frags = [&](int ks, int buf) {
            int k = ks * 16;
#pragma unroll
            for (int mi = 0; mi < 2; ++mi) {
                int row = wm * 32 + mi * 16 + a_r;
                uint32_t addr = abase_s + row * 128 +
                                (((k + a_c) * 2) ^ ((row & 7) * 16));
                ldsm4(af[buf][mi], addr);
            }
#pragma unroll
            for (int nh = 0; nh < 2; ++nh) {
                int row = wn * 32 + nh * 16 + b_r;
                uint32_t addr = bbase_s + row * 128 +
                                (((k + b_c) * 2) ^ ((row & 7) * 16));
                uint32_t r[4];
                ldsm4(r, addr);
                bf[buf][2 * nh + 0][0] = r[0]; bf[buf][2 * nh + 0][1] = r[1];
                bf[buf][2 * nh + 1][0] = r[2]; bf[buf][2 * nh + 1][1] = r[3];
            }
        };

        load_frags(0, 0);
#pragma unroll
        for (int ks = 0; ks < 4; ++ks) {
            int cur = ks & 1;
            if (ks < 3) load_frags(ks + 1, cur ^ 1);
#pragma unroll
            for (int mi = 0; mi < 2; ++mi)
#pragma unroll
                for (int ni = 0; ni < 4; ++ni)
                    mma16816(acc[mi][ni], af[cur][mi], bf[cur][ni]);
        }
    }

    int mb = wm * 32;
    int nb = bn * 64 + wn * 32;
    int qr = lane >> 2, qc = (lane & 3) * 2;
#pragma unroll
    for (int mi = 0; mi < 2; ++mi) {
#pragma unroll
        for (int ni = 0; ni < 4; ++ni) {
            int n = nb + ni * 8 + qc;
            float bv0 = bias[n], bv1 = bias[n + 1];
            float* c4 = acc[mi][ni];
#pragma unroll
            for (int half_ = 0; half_ < 2; ++half_) {
                int m = mb + mi * 16 + qr + half_ * 8;
                float v0 = c4[half_ * 2 + 0] + bv0;
                float v1 = c4[half_ * 2 + 1] + bv1;
                if (mode == 2) {
                    v0 += Add[(size_t)m * ldadd + n];
                    v1 += Add[(size_t)m * ldadd + n + 1];
                }
                *(float2*)&C[(size_t)m * ldc + n] = make_float2(v0, v1);
            }
        }
    }
}

__device__ void attention_dev(
    const float* __restrict__ qgh,
    const __half* __restrict__ keys,
    const float* __restrict__ att_v,
    const __half* __restrict__ features,
    __half* __restrict__ ctx,
    float* qs, float* av, float* sc, float* red)
{
    int b = blockIdx.x, tid = threadIdx.x;
    for (int i = tid; i < H_; i += 256) { qs[i] = qgh[b * 2048 + i]; av[i] = att_v[i]; }
    __syncthreads();

    int warp = tid >> 5, lane = tid & 31;
    const __half2* kpb = (const __half2*)(keys + (size_t)b * S_ * H_);
    for (int s = warp; s < S_; s += 8) {
        const __half2* kps = kpb + (size_t)s * (H_ / 2);
        float acc = 0.f;
        for (int i = lane; i < H_ / 2; i += 32) {
            float2 kv = __half22float2(kps[i]);
            acc += av[2 * i]     * tanh_fast(qs[2 * i]     + kv.x)
                 + av[2 * i + 1] * tanh_fast(qs[2 * i + 1] + kv.y);
        }
#pragma unroll
        for (int o = 16; o; o >>= 1) acc += __shfl_xor_sync(~0u, acc, o);
        if (!lane) sc[s] = acc;
    }
    __syncthreads();

    float m = -INFINITY;
    for (int s = tid; s < S_; s += 256) m = fmaxf(m, sc[s]);
#pragma unroll
    for (int o = 16; o; o >>= 1) m = fmaxf(m, __shfl_xor_sync(~0u, m, o));
    if (!lane) red[warp] = m;
    __syncthreads();
    m = red[0];
#pragma unroll
    for (int w = 1; w < 8; ++w) m = fmaxf(m, red[w]);
    __syncthreads();

    float ls = 0.f;
    for (int s = tid; s < S_; s += 256) { float e = __expf(sc[s] - m); sc[s] = e; ls += e; }
#pragma unroll
    for (int o = 16; o; o >>= 1) ls += __shfl_xor_sync(~0u, ls, o);
    if (!lane) red[warp] = ls;
    __syncthreads();
    float sum = 0.f;
#pragma unroll
    for (int w = 0; w < 8; ++w) sum += red[w];
    float inv = 1.f / sum;

    const __half* fb = features + (size_t)b * S_ * K_;
    for (int k = tid; k < K_; k += 256) {
        float acc = 0.f;
        for (int s = 0; s < S_; ++s)
            acc += sc[s] * __half2float(fb[(size_t)s * K_ + k]);
        ctx[b * K_ + k] = __float2half(acc * inv);
    }
    __syncthreads();
}

__device__ void gru_dev(
    const float* __restrict__ gi, const float* __restrict__ qgh,
    const float* __restrict__ hprev, float* __restrict__ hnew,
    __half* __restrict__ hnew16)
{
#pragma unroll
    for (int i = 0; i < 2; ++i) {
        int idx = blockIdx.x * 512 + i * 256 + threadIdx.x;
        int b = idx >> 9, j = idx & 511;
        const float* ghb = qgh + (size_t)b * 2048 + 512;
        int base = b * 1536 + j;
        float ir = gi[base], iz = gi[base + 512], in_ = gi[base + 1024];
        float hr = ghb[j], hz = ghb[512 + j], hn = ghb[1024 + j];
        float r = 1.f / (1.f + __expf(-(ir + hr)));
        float z = 1.f / (1.f + __expf(-(iz + hz)));
        float n = tanh_fast(in_ + r * hn);
        float v = (1.f - z) * n + z * hprev[idx];
        hnew[idx] = v;
        hnew16[idx] = __float2half(v);
    }
}

__global__ __launch_bounds__(256) void recurrence_kernel(
    const __half* __restrict__ wcat, const float* __restrict__ bcat,
    const __half* __restrict__ keys, const float* __restrict__ att_v,
    const __half* __restrict__ feat,
    const __half* __restrict__ wprime, const float* __restrict__ bias2,
    const float* __restrict__ gix,
    float* __restrict__ qgh, __half* __restrict__ ctx,
    float* __restrict__ gi,
    float* __restrict__ h, __half* __restrict__ h16)
{
    extern __shared__ __align__(16) char dsm[];
    float* qs  = (float*)dsm;       // attention view (time-disjoint with gemm)
    float* avv = qs + 512;
    float* sc  = avv + 512;
    float* red = sc + 200;

    for (int t = 0; t < TOUT; ++t) {
        const __half* h16prev = h16 + (size_t)t * B_ * H_;
        const float*  hprev   = h   + (size_t)t * B_ * H_;
        float*        hnew    = h   + (size_t)(t + 1) * B_ * H_;
        __half*       h16new  = h16 + (size_t)(t + 1) * B_ * H_;

        // A: [q | gh] = h @ [Wq ; Whh]^T + [0 ; bhh]   (32 tiles of 64 cols)
        if (blockIdx.x < 32)
            gemm_tile64_cp(h16prev, wcat, 512, qgh, 2048, bcat,
                           nullptr, 0, 1, blockIdx.x, dsm);
        grid_sync();

        // B: attention (1 block per batch row)
        attention_dev(qgh, keys, att_v, feat, ctx, qs, avv, sc, red);
        grid_sync();

        // C: gi = ctx @ W'^T + bias2 + gix_t           (24 tiles of 64 cols)
        if (blockIdx.x < 24)
            gemm_tile64_cp(ctx, wprime, 512, gi, 1536, bias2,
                           gix + (size_t)t * B_ * 3 * H_, 1536, 2,
                           blockIdx.x, dsm);
        grid_sync();

        // D: GRU gates
        gru_dev(gi, qgh, hprev, hnew, h16new);
        grid_sync();
    }
}

// -------- embedding gather -> fp16 -----------------------------------------
__global__ void gather_embed_h(const int* __restrict__ captions,
                               const float* __restrict__ emb,
                               __half* __restrict__ xe)
{
    int m = blockIdx.x;            // m = t*128 + b
    int t = m >> 7, b = m & 127;
    int cap = captions[b * TCAP + t];
    float4 v = ((const float4*)(emb + (size_t)cap * E_))[threadIdx.x];
    __half2* dst = (__half2*)(xe + (size_t)m * E_);
    dst[2 * threadIdx.x + 0] = __floats2half2_rn(v.x, v.y);
    dst[2 * threadIdx.x + 1] = __floats2half2_rn(v.z, v.w);
}

// -------- generic f32 -> f16 (n % 4 == 0) -----------------------------------
__global__ void f2h(const float* __restrict__ in, __half* __restrict__ out, int n)
{
    int i = (blockIdx.x * blockDim.x + threadIdx.x) * 4;
    if (i < n) {
        float4 v = *(const float4*)(in + i);
        ((__half2*)(out + i))[0] = __floats2half2_rn(v.x, v.y);
        ((__half2*)(out + i))[1] = __floats2half2_rn(v.z, v.w);
    }
}

// -------- gru_wih column-slice -> fp16 compact (offset 0 or 512) ------------
__global__ void conv_wih_part(const float* __restrict__ wih, __half* __restrict__ out,
                              int off)
{
    int n = blockIdx.x;            // 0..1535
    int t = threadIdx.x;           // 0..127
    float4 v = *(const float4*)(wih + (size_t)n * 1024 + off + t * 4);
    __half2* o = (__half2*)(out + (size_t)n * 512 + t * 4);
    o[0] = __floats2half2_rn(v.x, v.y);
    o[1] = __floats2half2_rn(v.z, v.w);
}

// -------- 512x512 transpose --------------------------------------------------
__global__ void transpose512(const float* __restrict__ in, float* __restrict__ out)
{
    __shared__ float tile[32][33];
    int x = blockIdx.x * 32 + threadIdx.x;
    int y = blockIdx.y * 32 + threadIdx.y;
#pragma unroll
    for (int j = 0; j < 4; ++j)
        tile[threadIdx.y + 8 * j][threadIdx.x] = in[(size_t)(y + 8 * j) * 512 + x];
    __syncthreads();
    int x2 = blockIdx.y * 32 + threadIdx.x;
    int y2 = blockIdx.x * 32 + threadIdx.y;
#pragma unroll
    for (int j = 0; j < 4; ++j)
        out[(size_t)(y2 + 8 * j) * 512 + x2] = tile[threadIdx.x][threadIdx.y + 8 * j];
}

// -------- merged prologue misc: bcat + bias2 + zero h + zero h16 ------------
__global__ void prep_misc(const float* __restrict__ bhh,
                          const float* __restrict__ wih,
                          const float* __restrict__ fc0b,
                          const float* __restrict__ bih,
                          float* __restrict__ bcat, float* __restrict__ bias2,
                          float* __restrict__ h, float* __restrict__ h16f)
{
    int idx = blockIdx.x * 256 + threadIdx.x;
    if (idx < 2048) {
        bcat[idx] = (idx < 512) ? 0.f : bhh[idx - 512];
    } else if (idx < 3584) {
        int n = idx - 2048;
        float s = 0.f;
        for (int j = 0; j < 512; ++j) s += wih[(size_t)n * 1024 + 512 + j] * fc0b[j];
        bias2[n] = s + bih[n];
    } else if (idx < 3584 + 65536) {
        h[idx - 3584] = 0.f;
    } else if (idx < 3584 + 65536 + 32768) {
        h16f[idx - 3584 - 65536] = 0.f;
    }
}

// ---------------- launch -----------------------------------------------------
extern "C" void kernel_launch(void* const* d_in, const int* in_sizes, int n_in,
                              void* d_out, int out_size)
{
    const float* features = (const float*)d_in[0];
    const int*   captions = (const int*)  d_in[1];
    const float* emb      = (const float*)d_in[2];
    const float* fc1_w    = (const float*)d_in[3];
    const float* fc1_b    = (const float*)d_in[4];
    const float* att_wq   = (const float*)d_in[5];
    const float* att_wk   = (const float*)d_in[6];
    const float* att_v    = (const float*)d_in[7];
    const float* fc0_w    = (const float*)d_in[8];
    const float* fc0_b    = (const float*)d_in[9];
    const float* gru_wih  = (const float*)d_in[10];
    const float* gru_whh  = (const float*)d_in[11];
    const float* gru_bih  = (const float*)d_in[12];
    const float* gru_bhh  = (const float*)d_in[13];
    const float* fc2_w    = (const float*)d_in[14];
    const float* fc2_b    = (const float*)d_in[15];
    float* out = (float*)d_out;

    float *gix, *h, *qgh, *gi, *bcat, *bias2, *fc0wT;
    __half *xe_h, *x_h, *fc1w_h, *wk_h, *feat_h, *keys_h, *wihx_h, *wihc_h;
    __half *fc0wT_h, *fc2w_h, *h16, *ctx_h, *wcat_h, *wprime_h;
    cudaGetSymbolAddress((void**)&gix,      g_gix);
    cudaGetSymbolAddress((void**)&h,        g_h);
    cudaGetSymbolAddress((void**)&qgh,      g_qgh);
    cudaGetSymbolAddress((void**)&gi,       g_gi);
    cudaGetSymbolAddress((void**)&bcat,     g_bcat);
    cudaGetSymbolAddress((void**)&bias2,    g_bias2);
    cudaGetSymbolAddress((void**)&fc0wT,    g_fc0wT);
    cudaGetSymbolAddress((void**)&xe_h,     g_xe_h);
    cudaGetSymbolAddress((void**)&x_h,      g_x_h);
    cudaGetSymbolAddress((void**)&fc1w_h,   g_fc1w_h);
    cudaGetSymbolAddress((void**)&wk_h,     g_wk_h);
    cudaGetSymbolAddress((void**)&feat_h,   g_feat_h);
    cudaGetSymbolAddress((void**)&keys_h,   g_keys_h);
    cudaGetSymbolAddress((void**)&wihx_h,   g_wihx_h);
    cudaGetSymbolAddress((void**)&wihc_h,   g_wihc_h);
    cudaGetSymbolAddress((void**)&fc0wT_h,  g_fc0wT_h);
    cudaGetSymbolAddress((void**)&fc2w_h,   g_fc2w_h);
    cudaGetSymbolAddress((void**)&h16,      g_h16);
    cudaGetSymbolAddress((void**)&ctx_h,    g_ctx_h);
    cudaGetSymbolAddress((void**)&wcat_h,   g_wcat_h);
    cudaGetSymbolAddress((void**)&wprime_h, g_wprime_h);

    cudaFuncSetAttribute(hgemm_nt, cudaFuncAttributeMaxDynamicSharedMemorySize,
                         HG_SMEM);
    cudaFuncSetAttribute(recurrence_kernel,
                         cudaFuncAttributeMaxDynamicSharedMemorySize, RC_SMEM);

    // ---- conversions ----
    gather_embed_h<<<TOUT * B_, 128>>>(captions, emb, xe_h);
    f2h<<<(B_ * S_ * K_ / 4 + 255) / 256, 256>>>(features, feat_h, B_ * S_ * K_);
    f2h<<<(H_ * K_ / 4 + 255) / 256, 256>>>(att_wk, wk_h, H_ * K_);
    // keys = f16(features @ att_wk^T)             (25088 x 512 x 512)
    hgemm_nt<<<dim3(H_ / 128, B_ * S_ / 128), 256, HG_SMEM>>>(
        feat_h, K_, wk_h, K_, keys_h, H_, K_, nullptr, 5);

    f2h<<<(H_ * E_ / 4 + 255) / 256, 256>>>(fc1_w, fc1w_h, H_ * E_);
    f2h<<<(V_ * H_ / 4 + 255) / 256, 256>>>(fc2_w, fc2w_h, V_ * H_);
    conv_wih_part<<<1536, 128>>>(gru_wih, wihx_h, 0);
    conv_wih_part<<<1536, 128>>>(gru_wih, wihc_h, 512);
    f2h<<<(512 * 512 / 4 + 255) / 256, 256>>>(att_wq, wcat_h, 512 * 512);
    f2h<<<(1536 * 512 / 4 + 255) / 256, 256>>>(gru_whh, wcat_h + 512 * 512,
                                               1536 * 512);
    transpose512<<<dim3(16, 16), dim3(32, 8)>>>(fc0_w, fc0wT);
    f2h<<<(512 * 512 / 4 + 255) / 256, 256>>>(fc0wT, fc0wT_h, 512 * 512);
    prep_misc<<<398, 256>>>(gru_bhh, gru_wih, fc0_b, gru_bih,
                            bcat, bias2, h, (float*)h16);

    // ---- prologue GEMMs ----
    // fc1: x_h = f16(xe @ fc1_w^T + b)            (1920 x 512 x 512)
    hgemm_nt<<<dim3(H_ / 128, TOUT * B_ / 128), 256, HG_SMEM>>>(
        xe_h, E_, fc1w_h, E_, x_h, H_, E_, fc1_b, 4);
    // gix = x @ Wih_x^T (f32)                     (1920 x 1536 x 512)
    hgemm_nt<<<dim3(3 * H_ / 128, TOUT * B_ / 128), 256, HG_SMEM>>>(
        x_h, H_, wihx_h, H_, gix, 3 * H_, H_, nullptr, 0);
    // W' = f16(Wih_ctx @ fc0_w)                   (1536 x 512 x 512)
    hgemm_nt<<<dim3(4, 12), 256, HG_SMEM>>>(
        wihc_h, 512, fc0wT_h, 512, wprime_h, 512, 512, nullptr, 5);

    // ---- recurrence: ONE persistent kernel, fast grid barriers ----
    recurrence_kernel<<<128, 256, RC_SMEM>>>(
        wcat_h, bcat, keys_h, att_v, feat_h,
        wprime_h, bias2, gix, qgh, ctx_h, gi, h, h16);

    // ---- logits: pipelined HMMA (1920 x 32000 x 512), f32 + bias + remap ----
    hgemm_nt<<<dim3(V_ / 128, TOUT * B_ / 128), 256, HG_SMEM>>>(
        h16 + B_ * H_, H_, fc2w_h, H_, out, V_, H_, fc2_b, 3);
}

// round 14
// speedup vs baseline: 1.5372x; 1.5372x over previous
#include <cuda_runtime.h>
#include <cuda_fp16.h>
#include <cuda_bf16.h>
#include <math.h>
#include <stdint.h>

// Problem dims
#define B_   128
#define S_   196
#define K_   512
#define TCAP 16
#define TOUT 15
#define V_   32000
#define E_   512
#define H_   512

// ---------------- scratch (device globals; allocation-free) ----------------
__device__ float g_gix[TOUT * B_ * 3 * H_];        // x_t @ Wx^T  (t*128+b, 1536)
__device__ float g_h[(TOUT + 1) * B_ * H_];        // h_0..h_15 fp32 master
__device__ float g_qgh[B_ * 2048];                 // per-step [q | gh]
__device__ float g_gi[B_ * 3 * H_];
__device__ float g_bcat[2048];                     // [0 ; gru_bhh]
__device__ float g_bias2[1536];                    // Wih_ctx@fc0_b + b_ih
__device__ float g_fc0wT[512 * 512];

// fp16 operands
__device__ __half g_xe_h[TOUT * B_ * E_];
__device__ __half g_x_h[TOUT * B_ * H_];
__device__ __half g_fc1w_h[H_ * E_];
__device__ __half g_wk_h[H_ * K_];
__device__ __half g_feat_h[(size_t)B_ * S_ * K_];
__device__ __half g_keys_h[(size_t)B_ * S_ * H_];
__device__ __half g_wihx_h[1536 * 512];
__device__ __half g_wihc_h[1536 * 512];
__device__ __half g_fc0wT_h[512 * 512];
__device__ __half g_fc2w_h[(size_t)V_ * H_];
__device__ __half g_h16[(TOUT + 1) * B_ * H_];     // fp16 h, slot 0 = zeros
__device__ __half g_ctx_h[B_ * K_];
__device__ __half g_wcat_h[2048 * 512];            // [att_wq ; gru_whh] fp16
__device__ __half g_wprime_h[1536 * 512];

// grid-barrier state (zero-initialized)
__device__ unsigned g_bar_count;
__device__ volatile unsigned g_bar_gen;

// ---------------- fast math helpers ----------------------------------------
__device__ __forceinline__ float tanh_fast(float x) {
    float y;
    asm("tanh.approx.f32 %0, %1;" : "=f"(y) : "f"(x));
    return y;
}

// ========================= mma helpers =====================================
__device__ __forceinline__ void ldsm4(uint32_t* r, uint32_t addr) {
    asm volatile("ldmatrix.sync.aligned.m8n8.x4.shared.b16 {%0,%1,%2,%3}, [%4];"
        : "=r"(r[0]), "=r"(r[1]), "=r"(r[2]), "=r"(r[3]) : "r"(addr));
}
__device__ __forceinline__ void mma16816(float* c, const uint32_t* a, const uint32_t* b) {
    asm volatile("mma.sync.aligned.m16n8k16.row.col.f32.f16.f16.f32 "
        "{%0,%1,%2,%3}, {%4,%5,%6,%7}, {%8,%9}, {%0,%1,%2,%3};"
        : "+f"(c[0]), "+f"(c[1]), "+f"(c[2]), "+f"(c[3])
        : "r"(a[0]), "r"(a[1]), "r"(a[2]), "r"(a[3]), "r"(b[0]), "r"(b[1]));
}
__device__ __forceinline__ void cpasync16(uint32_t dst, const void* src) {
    asm volatile("cp.async.cg.shared.global [%0], [%1], 16;" :: "r"(dst), "l"(src));
}

// ============ fp16 HMMA NT GEMM, 3-stage cp.async pipeline (R7 config) =====
// C[M,N] = A[M,K]h * B[N,K]h^T ; BM=BN=128, BK=64, 256 thr, 8 warps (2m x 4n)
// Dynamic smem: 3 stages x (A 16KB + B 16KB) = 96KB. XOR-swizzled 128B rows.
// modes: 0 plain f32, 3 +bias remap (m=t*128+b -> row b*15+t),
//        4 +bias store fp16, 5 plain store fp16
#define HG_SMEM (3 * 32768)

__global__ __launch_bounds__(256) void hgemm_nt(
    const __half* __restrict__ A, int lda,
    const __half* __restrict__ B, int ldb,
    void* __restrict__ Cv, int ldc, int K,
    const float* __restrict__ bias, int mode)
{
    extern __shared__ __half sm[];
    uint32_t sb = (uint32_t)__cvta_generic_to_shared(sm);
    const int tid = threadIdx.x, lane = tid & 31, warp = tid >> 5;
    const int wm = warp & 1, wn = warp >> 1;
    const int bn = blockIdx.x, bm = blockIdx.y;

    const __half* Abase = A + (size_t)(bm * 128) * lda;
    const __half* Bbase = B + (size_t)(bn * 128) * ldb;

    auto load_tile = [&](int kt, int st) {
        uint32_t abase_s = sb + st * 32768;
        uint32_t bbase_s = abase_s + 16384;
#pragma unroll
        for (int i = 0; i < 4; ++i) {
            int cid = i * 256 + tid;
            int row = cid >> 3, c8 = cid & 7;
            uint32_t soff = row * 128 + ((c8 * 16) ^ ((row & 7) * 16));
            cpasync16(abase_s + soff, Abase + (size_t)row * lda + kt * 64 + c8 * 8);
            cpasync16(bbase_s + soff, Bbase + (size_t)row * ldb + kt * 64 + c8 * 8);
        }
        asm volatile("cp.async.commit_group;" ::: "memory");
    };

    float acc[4][4][4] = {};
    const int a_r = ((lane >> 3) & 1) * 8 + (lane & 7);
    const int a_c = (lane >> 4) * 8;
    const int b_r = ((lane >> 4) & 1) * 8 + (lane & 7);
    const int b_c = ((lane >> 3) & 1) * 8;

    const int nkt = K / 64;
    load_tile(0, 0);
    if (nkt > 1) load_tile(1, 1);

    for (int kt = 0; kt < nkt; ++kt) {
        int st = kt % 3;
        if (kt + 1 < nkt) {
            asm volatile("cp.async.wait_group 1;" ::: "memory");
        } else {
            asm volatile("cp.async.wait_group 0;" ::: "memory");
        }
        __syncthreads();
        if (kt + 2 < nkt) load_tile(kt + 2, (kt + 2) % 3);

        uint32_t abase_s = sb + st * 32768;
        uint32_t bbase_s = abase_s + 16384;
#pragma unroll
        for (int ks = 0; ks < 4; ++ks) {
            int k = ks * 16;
            uint32_t af[4][4], bf[4][2];
#pragma unroll
            for (int mi = 0; mi < 4; ++mi) {
                int row = wm * 64 + mi * 16 + a_r;
                uint32_t addr = abase_s + row * 128 +
                                (((k + a_c) * 2) ^ ((row & 7) * 16));
                ldsm4(af[mi], addr);
            }
#pragma unroll
            for (int nh = 0; nh < 2; ++nh) {
                int row = wn * 32 + nh * 16 + b_r;
                uint32_t addr = bbase_s + row * 128 +
                                (((k + b_c) * 2) ^ ((row & 7) * 16));
                uint32_t r[4];
                ldsm4(r, addr);
                bf[2 * nh + 0][0] = r[0]; bf[2 * nh + 0][1] = r[1];
                bf[2 * nh + 1][0] = r[2]; bf[2 * nh + 1][1] = r[3];
            }
#pragma unroll
            for (int mi = 0; mi < 4; ++mi)
#pragma unroll
                for (int ni = 0; ni < 4; ++ni)
                    mma16816(acc[mi][ni], af[mi], bf[ni]);
        }
    }

    const int mb = bm * 128 + wm * 64;
    const int nb = bn * 128 + wn * 32;
    const int qr = lane >> 2, qc = (lane & 3) * 2;
#pragma unroll
    for (int mi = 0; mi < 4; ++mi) {
#pragma unroll
        for (int ni = 0; ni < 4; ++ni) {
            int n = nb + ni * 8 + qc;
            float bv = 0.f, bv2 = 0.f;
            if (mode == 3 || mode == 4) { bv = bias[n]; bv2 = bias[n + 1]; }
            float* c4 = acc[mi][ni];
#pragma unroll
            for (int half_ = 0; half_ < 2; ++half_) {
                int m = mb + mi * 16 + qr + half_ * 8;
                float v0 = c4[half_ * 2 + 0] + bv;
                float v1 = c4[half_ * 2 + 1] + bv2;
                if (mode == 4 || mode == 5) {
                    __half* C = (__half*)Cv;
                    *(__half2*)&C[(size_t)m * ldc + n] =
                        __halves2half2(__float2half(v0), __float2half(v1));
                } else if (mode == 3) {
                    int b = m & 127, t = m >> 7;
                    float* C = (float*)Cv;
                    *(float2*)&C[((size_t)b * TOUT + t) * ldc + n] = make_float2(v0, v1);
                } else {
                    float* C = (float*)Cv;
                    *(float2*)&C[(size_t)m * ldc + n] = make_float2(v0, v1);
                }
            }
        }
    }
}

// ============ fp16 HMMA NT GEMM, 2-stage variant for 2 CTA/SM ==============
// Same math/order as hgemm_nt; 2 stages x 32KB = 64KB dynamic smem so two
// CTAs co-reside per SM (cross-CTA latency hiding). Used for logits only.
#define HG2_SMEM (2 * 32768)

__global__ __launch_bounds__(256, 2) void hgemm_nt2(
    const __half* __restrict__ A, int lda,
    const __half* __restrict__ B, int ldb,
    void* __restrict__ Cv, int ldc, int K,
    const float* __restrict__ bias, int mode)
{
    extern __shared__ __half sm[];
    uint32_t sb = (uint32_t)__cvta_generic_to_shared(sm);
    const int tid = threadIdx.x, lane = tid & 31, warp = tid >> 5;
    const int wm = warp & 1, wn = warp >> 1;
    const int bn = blockIdx.x, bm = blockIdx.y;

    const __half* Abase = A + (size_t)(bm * 128) * lda;
    const __half* Bbase = B + (size_t)(bn * 128) * ldb;

    auto load_tile = [&](int kt, int st) {
        uint32_t abase_s = sb + st * 32768;
        uint32_t bbase_s = abase_s + 16384;
#pragma unroll
        for (int i = 0; i < 4; ++i) {
            int cid = i * 256 + tid;
            int row = cid >> 3, c8 = cid & 7;
            uint32_t soff = row * 128 + ((c8 * 16) ^ ((row & 7) * 16));
            cpasync16(abase_s + soff, Abase + (size_t)row * lda + kt * 64 + c8 * 8);
            cpasync16(bbase_s + soff, Bbase + (size_t)row * ldb + kt * 64 + c8 * 8);
        }
        asm volatile("cp.async.commit_group;" ::: "memory");
    };

    float acc[4][4][4] = {};
    const int a_r = ((lane >> 3) & 1) * 8 + (lane & 7);
    const int a_c = (lane >> 4) * 8;
    const int b_r = ((lane >> 4) & 1) * 8 + (lane & 7);
    const int b_c = ((lane >> 3) & 1) * 8;

    const int nkt = K / 64;
    load_tile(0, 0);

    for (int kt = 0; kt < nkt; ++kt) {
        int st = kt & 1;
        if (kt + 1 < nkt) {
            load_tile(kt + 1, st ^ 1);
            asm volatile("cp.async.wait_group 1;" ::: "memory");
        } else {
            asm volatile("cp.async.wait_group 0;" ::: "memory");
        }
        __syncthreads();

        uint32_t abase_s = sb + st * 32768;
        uint32_t bbase_s = abase_s + 16384;
#pragma unroll
        for (int ks = 0; ks < 4; ++ks) {
            int k = ks * 16;
            uint32_t af[4][4], bf[4][2];
#pragma unroll
            for (int mi = 0; mi < 4; ++mi) {
                int row = wm * 64 + mi * 16 + a_r;
                uint32_t addr = abase_s + row * 128 +
                                (((k + a_c) * 2) ^ ((row & 7) * 16));
                ldsm4(af[mi], addr);
            }
#pragma unroll
            for (int nh = 0; nh < 2; ++nh) {
                int row = wn * 32 + nh * 16 + b_r;
                uint32_t addr = bbase_s + row * 128 +
                                (((k + b_c) * 2) ^ ((row & 7) * 16));
                uint32_t r[4];
                ldsm4(r, addr);
                bf[2 * nh + 0][0] = r[0]; bf[2 * nh + 0][1] = r[1];
                bf[2 * nh + 1][0] = r[2]; bf[2 * nh + 1][1] = r[3];
            }
#pragma unroll
            for (int mi = 0; mi < 4; ++mi)
#pragma unroll
                for (int ni = 0; ni < 4; ++ni)
                    mma16816(acc[mi][ni], af[mi], bf[ni]);
        }
        __syncthreads();   // stage st is free for the load in iteration kt+1
    }

    const int mb = bm * 128 + wm * 64;
    const int nb = bn * 128 + wn * 32;
    const int qr = lane >> 2, qc = (lane & 3) * 2;
#pragma unroll
    for (int mi = 0; mi < 4; ++mi) {
#pragma unroll
        for (int ni = 0; ni < 4; ++ni) {
            int n = nb + ni * 8 + qc;
            float bv = 0.f, bv2 = 0.f;
            if (mode == 3 || mode == 4) { bv = bias[n]; bv2 = bias[n + 1]; }
            float* c4 = acc[mi][ni];
#pragma unroll
            for (int half_ = 0; half_ < 2; ++half_) {
                int m = mb + mi * 16 + qr + half_ * 8;
                float v0 = c4[half_ * 2 + 0] + bv;
                float v1 = c4[half_ * 2 + 1] + bv2;
                if (mode == 4 || mode == 5) {
                    __half* C = (__half*)Cv;
                    *(__half2*)&C[(size_t)m * ldc + n] =
                        __halves2half2(__float2half(v0), __float2half(v1));
                } else if (mode == 3) {
                    int b = m & 127, t = m >> 7;
                    float* C = (float*)Cv;
                    *(float2*)&C[((size_t)b * TOUT + t) * ldc + n] = make_float2(v0, v1);
                } else {
                    float* C = (float*)Cv;
                    *(float2*)&C[(size_t)m * ldc + n] = make_float2(v0, v1);
                }
            }
        }
    }
}

// ====================== persistent recurrence kernel (R11 proven) ===========
// grid = 128 CTAs x 256 thr (all resident). Software grid barrier.
// Dynamic smem 73728B: gemm 3 stages x (A 16KB + B 8KB); attention aliases it.

#define RC_SMEM 73728

__device__ __forceinline__ void grid_sync() {
    __syncthreads();
    if (threadIdx.x == 0) {
        __threadfence();
        unsigned gen = g_bar_gen;
        if (atomicAdd(&g_bar_count, 1u) == gridDim.x - 1) {
            g_bar_count = 0;
            __threadfence();
            g_bar_gen = gen + 1;
        } else {
            while (g_bar_gen == gen) { }
            __threadfence();
        }
    }
    __syncthreads();
}

// 64-col GEMM tile with cp.async pipeline:
// C[128, 64 cols at tile bn] = A[128,512]h * B[bn-rows,512]h^T (+bias,+Add)
// 3 stages x (A 128x64h = 16KB, B 64x64h = 8KB). Same K order as before.
__device__ void gemm_tile64_cp(
    const __half* __restrict__ A,
    const __half* __restrict__ B, int ldb,
    float* __restrict__ C, int ldc,
    const float* __restrict__ bias,
    const float* __restrict__ Add, int ldadd, int mode, int bn,
    char* dsm)
{
    uint32_t sb = (uint32_t)__cvta_generic_to_shared(dsm);
    int tid = threadIdx.x, lane = tid & 31, warp = tid >> 5;
    int wm = warp >> 1, wn = warp & 1;

    const __half* Bbase = B + (size_t)(bn * 64) * ldb;

    auto load_tile = [&](int kt, int st) {
        uint32_t abase_s = sb + st * 24576;
        uint32_t bbase_s = abase_s + 16384;
#pragma unroll
        for (int i = 0; i < 4; ++i) {               // A: 1024 16B chunks
            int cid = i * 256 + tid;
            int row = cid >> 3, c8 = cid & 7;
            uint32_t soff = row * 128 + ((c8 * 16) ^ ((row & 7) * 16));
            cpasync16(abase_s + soff, A + (size_t)row * 512 + kt * 64 + c8 * 8);
        }
#pragma unroll
        for (int i = 0; i < 2; ++i) {               // B: 512 16B chunks
            int cid = i * 256 + tid;
            int row = cid >> 3, c8 = cid & 7;
            uint32_t soff = row * 128 + ((c8 * 16) ^ ((row & 7) * 16));
            cpasync16(bbase_s + soff, Bbase + (size_t)row * ldb + kt * 64 + c8 * 8);
        }
        asm volatile("cp.async.commit_group;" ::: "memory");
    };

    float acc[2][4][4] = {};
    int a_r = ((lane >> 3) & 1) * 8 + (lane & 7);
    int a_c = (lane >> 4) * 8;
    int b_r = ((lane >> 4) & 1) * 8 + (lane & 7);
    int b_c = ((lane >> 3) & 1) * 8;

    load_tile(0, 0);
    load_tile(1, 1);

    for (int kt = 0; kt < 8; ++kt) {
        int st = kt % 3;
        if (kt + 1 < 8) {
            asm volatile("cp.async.wait_group 1;" ::: "memory");
        } else {
            asm volatile("cp.async.wait_group 0;" ::: "memory");
        }
        __syncthreads();
        if (kt + 2 < 8) load_tile(kt + 2, (kt + 2) % 3);

        uint32_t abase_s = sb + st * 24576;
        uint32_t bbase_s = abase_s + 16384;
#pragma unroll
        for (int ks = 0; ks < 4; ++ks) {
            int k = ks * 16;
            uint32_t af[2][4], bf[4][2];
#pragma unroll
            for (int mi = 0; mi < 2; ++mi) {
                int row = wm * 32 + mi * 16 + a_r;
                uint32_t addr = abase_s + row * 128 +
                                (((k + a_c) * 2) ^ ((row & 7) * 16));
                ldsm4(af[mi], addr);
            }
#pragma unroll
            for (int nh = 0; nh < 2; ++nh) {
                int row = wn * 32 + nh * 16 + b_r;
                uint32_t addr = bbase_s + row * 128 +
                                (((k + b_c) * 2) ^ ((row & 7) * 16));
                uint32_t r[4];
                ldsm4(r, addr);
                bf[2 * nh + 0][0] = r[0]; bf[2 * nh + 0][1] = r[1];
                bf[2 * nh + 1][0] = r[2]; bf[2 * nh + 1][1] = r[3];
            }
#pragma unroll
            for (int mi = 0; mi < 2; ++mi)
#pragma unroll
                for (int ni = 0; ni < 4; ++ni)
                    mma16816(acc[mi][ni], af[mi], bf[ni]);
        }
    }

    int mb = wm * 32;
    int nb = bn * 64 + wn * 32;
    int qr = lane >> 2, qc = (lane & 3) * 2;
#pragma unroll
    for (int mi = 0; mi < 2; ++mi) {
#pragma unroll
        for (int ni = 0; ni < 4; ++ni) {
            int n = nb + ni * 8 + qc;
            float bv0 = bias[n], bv1 = bias[n + 1];
            float* c4 = acc[mi][ni];
#pragma unroll
            for (int half_ = 0; half_ < 2; ++half_) {
                int m = mb + mi * 16 + qr + half_ * 8;
                float v0 = c4[half_ * 2 + 0] + bv0;
                float v1 = c4[half_ * 2 + 1] + bv1;
                if (mode == 2) {
                    v0 += Add[(size_t)m * ldadd + n];
                    v1 += Add[(size_t)m * ldadd + n + 1];
                }
                *(float2*)&C[(size_t)m * ldc + n] = make_float2(v0, v1);
            }
        }
    }
}

__device__ void attention_dev(
    const float* __restrict__ qgh,
    const __half* __restrict__ keys,
    const float* __restrict__ att_v,
    const __half* __restrict__ features,
    __half* __restrict__ ctx,
    float* qs, float* av, float* sc, float* red)
{
    int b = blockIdx.x, tid = threadIdx.x;
    for (int i = tid; i < H_; i += 256) { qs[i] = qgh[b * 2048 + i]; av[i] = att_v[i]; }
    __syncthreads();

    int warp = tid >> 5, lane = tid & 31;
    const __half2* kpb = (const __half2*)(keys + (size_t)b * S_ * H_);
    for (int s = warp; s < S_; s += 8) {
        const __half2* kps = kpb + (size_t)s * (H_ / 2);
        float acc = 0.f;
        for (int i = lane; i < H_ / 2; i += 32) {
            float2 kv = __half22float2(kps[i]);
            acc += av[2 * i]     * tanh_fast(qs[2 * i]     + kv.x)
                 + av[2 * i + 1] * tanh_fast(qs[2 * i + 1] + kv.y);
        }
#pragma unroll
        for (int o = 16; o; o >>= 1) acc += __shfl_xor_sync(~0u, acc, o);
        if (!lane) sc[s] = acc;
    }
    __syncthreads();

    float m = -INFINITY;
    for (int s = tid; s < S_; s += 256) m = fmaxf(m, sc[s]);
#pragma unroll
    for (int o = 16; o; o >>= 1) m = fmaxf(m, __shfl_xor_sync(~0u, m, o));
    if (!lane) red[warp] = m;
    __syncthreads();
    m = red[0];
#pragma unroll
    for (int w = 1; w < 8; ++w) m = fmaxf(m, red[w]);
    __syncthreads();

    float ls = 0.f;
    for (int s = tid; s < S_; s += 256) { float e = __expf(sc[s] - m); sc[s] = e; ls += e; }
#pragma unroll
    for (int o = 16; o; o >>= 1) ls += __shfl_xor_sync(~0u, ls, o);
    if (!lane) red[warp] = ls;
    __syncthreads();
    float sum = 0.f;
#pragma unroll
    for (int w = 0; w < 8; ++w) sum += red[w];
    float inv = 1.f / sum;

    const __half* fb = features + (size_t)b * S_ * K_;
    for (int k = tid; k < K_; k += 256) {
        float acc = 0.f;
        for (int s = 0; s < S_; ++s)
            acc += sc[s] * __half2float(fb[(size_t)s * K_ + k]);
        ctx[b * K_ + k] = __float2half(acc * inv);
    }
    __syncthreads();
}

__device__ void gru_dev(
    const float* __restrict__ gi, const float* __restrict__ qgh,
    const float* __restrict__ hprev, float* __restrict__ hnew,
    __half* __restrict__ hnew16)
{
#pragma unroll
    for (int i = 0; i < 2; ++i) {
        int idx = blockIdx.x * 512 + i * 256 + threadIdx.x;
        int b = idx >> 9, j = idx & 511;
        const float* ghb = qgh + (size_t)b * 2048 + 512;
        int base = b * 1536 + j;
        float ir = gi[base], iz = gi[base + 512], in_ = gi[base + 1024];
        float hr = ghb[j], hz = ghb[512 + j], hn = ghb[1024 + j];
        float r = 1.f / (1.f + __expf(-(ir + hr)));
        float z = 1.f / (1.f + __expf(-(iz + hz)));
        float n = tanh_fast(in_ + r * hn);
        float v = (1.f - z) * n + z * hprev[idx];
        hnew[idx] = v;
        hnew16[idx] = __float2half(v);
    }
}

__global__ __launch_bounds__(256) void recurrence_kernel(
    const __half* __restrict__ wcat, const float* __restrict__ bcat,
    const __half* __restrict__ keys, const float* __restrict__ att_v,
    const __half* __restrict__ feat,
    const __half* __restrict__ wprime, const float* __restrict__ bias2,
    const float* __restrict__ gix,
    float* __restrict__ qgh, __half* __restrict__ ctx,
    float* __restrict__ gi,
    float* __restrict__ h, __half* __restrict__ h16)
{
    extern __shared__ __align__(16) char dsm[];
    float* qs  = (float*)dsm;       // attention view (time-disjoint with gemm)
    float* avv = qs + 512;
    float* sc  = avv + 512;
    float* red = sc + 200;

    for (int t = 0; t < TOUT; ++t) {
        const __half* h16prev = h16 + (size_t)t * B_ * H_;
        const float*  hprev   = h   + (size_t)t * B_ * H_;
        float*        hnew    = h   + (size_t)(t + 1) * B_ * H_;
        __half*       h16new  = h16 + (size_t)(t + 1) * B_ * H_;

        // A: [q | gh] = h @ [Wq ; Whh]^T + [0 ; bhh]   (32 tiles of 64 cols)
        if (blockIdx.x < 32)
            gemm_tile64_cp(h16prev, wcat, 512, qgh, 2048, bcat,
                           nullptr, 0, 1, blockIdx.x, dsm);
        grid_sync();

        // B: attention (1 block per batch row)
        attention_dev(qgh, keys, att_v, feat, ctx, qs, avv, sc, red);
        grid_sync();

        // C: gi = ctx @ W'^T + bias2 + gix_t           (24 tiles of 64 cols)
        if (blockIdx.x < 24)
            gemm_tile64_cp(ctx, wprime, 512, gi, 1536, bias2,
                           gix + (size_t)t * B_ * 3 * H_, 1536, 2,
                           blockIdx.x, dsm);
        grid_sync();

        // D: GRU gates
        gru_dev(gi, qgh, hprev, hnew, h16new);
        grid_sync();
    }
}

// -------- embedding gather -> fp16 -----------------------------------------
__global__ void gather_embed_h(const int* __restrict__ captions,
                               const float* __restrict__ emb,
                               __half* __restrict__ xe)
{
    int m = blockIdx.x;            // m = t*128 + b
    int t = m >> 7, b = m & 127;
    int cap = captions[b * TCAP + t];
    float4 v = ((const float4*)(emb + (size_t)cap * E_))[threadIdx.x];
    __half2* dst = (__half2*)(xe + (size_t)m * E_);
    dst[2 * threadIdx.x + 0] = __floats2half2_rn(v.x, v.y);
    dst[2 * threadIdx.x + 1] = __floats2half2_rn(v.z, v.w);
}

// -------- generic f32 -> f16 (n % 4 == 0) -----------------------------------
__global__ void f2h(const float* __restrict__ in, __half* __restrict__ out, int n)
{
    int i = (blockIdx.x * blockDim.x + threadIdx.x) * 4;
    if (i < n) {
        float4 v = *(const float4*)(in + i);
        ((__half2*)(out + i))[0] = __floats2half2_rn(v.x, v.y);
        ((__half2*)(out + i))[1] = __floats2half2_rn(v.z, v.w);
    }
}

// -------- gru_wih column-slice -> fp16 compact (offset 0 or 512) ------------
__global__ void conv_wih_part(const float* __restrict__ wih, __half* __restrict__ out,
                              int off)
{
    int n = blockIdx.x;            // 0..1535
    int t = threadIdx.x;           // 0..127
    float4 v = *(const float4*)(wih + (size_t)n * 1024 + off + t * 4);
    __half2* o = (__half2*)(out + (size_t)n * 512 + t * 4);
    o[0] = __floats2half2_rn(v.x, v.y);
    o[1] = __floats2half2_rn(v.z, v.w);
}

// -------- 512x512 transpose --------------------------------------------------
__global__ void transpose512(const float* __restrict__ in, float* __restrict__ out)
{
    __shared__ float tile[32][33];
    int x = blockIdx.x * 32 + threadIdx.x;
    int y = blockIdx.y * 32 + threadIdx.y;
#pragma unroll
    for (int j = 0; j < 4; ++j)
        tile[threadIdx.y + 8 * j][threadIdx.x] = in[(size_t)(y + 8 * j) * 512 + x];
    __syncthreads();
    int x2 = blockIdx.y * 32 + threadIdx.x;
    int y2 = blockIdx.x * 32 + threadIdx.y;
#pragma unroll
    for (int j = 0; j < 4; ++j)
        out[(size_t)(y2 + 8 * j) * 512 + x2] = tile[threadIdx.x][threadIdx.y + 8 * j];
}

// -------- merged prologue misc: bcat + bias2 + zero h + zero h16 ------------
__global__ void prep_misc(const float* __restrict__ bhh,
                          const float* __restrict__ wih,
                          const float* __restrict__ fc0b,
                          const float* __restrict__ bih,
                          float* __restrict__ bcat, float* __restrict__ bias2,
                          float* __restrict__ h, float* __restrict__ h16f)
{
    int idx = blockIdx.x * 256 + threadIdx.x;
    if (idx < 2048) {
        bcat[idx] = (idx < 512) ? 0.f : bhh[idx - 512];
    } else if (idx < 3584) {
        int n = idx - 2048;
        float s = 0.f;
        for (int j = 0; j < 512; ++j) s += wih[(size_t)n * 1024 + 512 + j] * fc0b[j];
        bias2[n] = s + bih[n];
    } else if (idx < 3584 + 65536) {
        h[idx - 3584] = 0.f;
    } else if (idx < 3584 + 65536 + 32768) {
        h16f[idx - 3584 - 65536] = 0.f;
    }
}

// ---------------- launch -----------------------------------------------------
extern "C" void kernel_launch(void* const* d_in, const int* in_sizes, int n_in,
                              void* d_out, int out_size)
{
    const float* features = (const float*)d_in[0];
    const int*   captions = (const int*)  d_in[1];
    const float* emb      = (const float*)d_in[2];
    const float* fc1_w    = (const float*)d_in[3];
    const float* fc1_b    = (const float*)d_in[4];
    const float* att_wq   = (const float*)d_in[5];
    const float* att_wk   = (const float*)d_in[6];
    const float* att_v    = (const float*)d_in[7];
    const float* fc0_w    = (const float*)d_in[8];
    const float* fc0_b    = (const float*)d_in[9];
    const float* gru_wih  = (const float*)d_in[10];
    const float* gru_whh  = (const float*)d_in[11];
    const float* gru_bih  = (const float*)d_in[12];
    const float* gru_bhh  = (const float*)d_in[13];
    const float* fc2_w    = (const float*)d_in[14];
    const float* fc2_b    = (const float*)d_in[15];
    float* out = (float*)d_out;

    float *gix, *h, *qgh, *gi, *bcat, *bias2, *fc0wT;
    __half *xe_h, *x_h, *fc1w_h, *wk_h, *feat_h, *keys_h, *wihx_h, *wihc_h;
    __half *fc0wT_h, *fc2w_h, *h16, *ctx_h, *wcat_h, *wprime_h;
    cudaGetSymbolAddress((void**)&gix,      g_gix);
    cudaGetSymbolAddress((void**)&h,        g_h);
    cudaGetSymbolAddress((void**)&qgh,      g_qgh);
    cudaGetSymbolAddress((void**)&gi,       g_gi);
    cudaGetSymbolAddress((void**)&bcat,     g_bcat);
    cudaGetSymbolAddress((void**)&bias2,    g_bias2);
    cudaGetSymbolAddress((void**)&fc0wT,    g_fc0wT);
    cudaGetSymbolAddress((void**)&xe_h,     g_xe_h);
    cudaGetSymbolAddress((void**)&x_h,      g_x_h);
    cudaGetSymbolAddress((void**)&fc1w_h,   g_fc1w_h);
    cudaGetSymbolAddress((void**)&wk_h,     g_wk_h);
    cudaGetSymbolAddress((void**)&feat_h,   g_feat_h);
    cudaGetSymbolAddress((void**)&keys_h,   g_keys_h);
    cudaGetSymbolAddress((void**)&wihx_h,   g_wihx_h);
    cudaGetSymbolAddress((void**)&wihc_h,   g_wihc_h);
    cudaGetSymbolAddress((void**)&fc0wT_h,  g_fc0wT_h);
    cudaGetSymbolAddress((void**)&fc2w_h,   g_fc2w_h);
    cudaGetSymbolAddress((void**)&h16,      g_h16);
    cudaGetSymbolAddress((void**)&ctx_h,    g_ctx_h);
    cudaGetSymbolAddress((void**)&wcat_h,   g_wcat_h);
    cudaGetSymbolAddress((void**)&wprime_h, g_wprime_h);

    cudaFuncSetAttribute(hgemm_nt, cudaFuncAttributeMaxDynamicSharedMemorySize,
                         HG_SMEM);
    cudaFuncSetAttribute(hgemm_nt2, cudaFuncAttributeMaxDynamicSharedMemorySize,
                         HG2_SMEM);
    cudaFuncSetAttribute(recurrence_kernel,
                         cudaFuncAttributeMaxDynamicSharedMemorySize, RC_SMEM);

    // ---- conversions ----
    gather_embed_h<<<TOUT * B_, 128>>>(captions, emb, xe_h);
    f2h<<<(B_ * S_ * K_ / 4 + 255) / 256, 256>>>(features, feat_h, B_ * S_ * K_);
    f2h<<<(H_ * K_ / 4 + 255) / 256, 256>>>(att_wk, wk_h, H_ * K_);
    // keys = f16(features @ att_wk^T)             (25088 x 512 x 512)
    hgemm_nt<<<dim3(H_ / 128, B_ * S_ / 128), 256, HG_SMEM>>>(
        feat_h, K_, wk_h, K_, keys_h, H_, K_, nullptr, 5);

    f2h<<<(H_ * E_ / 4 + 255) / 256, 256>>>(fc1_w, fc1w_h, H_ * E_);
    f2h<<<(V_ * H_ / 4 + 255) / 256, 256>>>(fc2_w, fc2w_h, V_ * H_);
    conv_wih_part<<<1536, 128>>>(gru_wih, wihx_h, 0);
    conv_wih_part<<<1536, 128>>>(gru_wih, wihc_h, 512);
    f2h<<<(512 * 512 / 4 + 255) / 256, 256>>>(att_wq, wcat_h, 512 * 512);
    f2h<<<(1536 * 512 / 4 + 255) / 256, 256>>>(gru_whh, wcat_h + 512 * 512,
                                               1536 * 512);
    transpose512<<<dim3(16, 16), dim3(32, 8)>>>(fc0_w, fc0wT);
    f2h<<<(512 * 512 / 4 + 255) / 256, 256>>>(fc0wT, fc0wT_h, 512 * 512);
    prep_misc<<<398, 256>>>(gru_bhh, gru_wih, fc0_b, gru_bih,
                            bcat, bias2, h, (float*)h16);

    // ---- prologue GEMMs ----
    // fc1: x_h = f16(xe @ fc1_w^T + b)            (1920 x 512 x 512)
    hgemm_nt<<<dim3(H_ / 128, TOUT * B_ / 128), 256, HG_SMEM>>>(
        xe_h, E_, fc1w_h, E_, x_h, H_, E_, fc1_b, 4);
    // gix = x @ Wih_x^T (f32)                     (1920 x 1536 x 512)
    hgemm_nt<<<dim3(3 * H_ / 128, TOUT * B_ / 128), 256, HG_SMEM>>>(
        x_h, H_, wihx_h, H_, gix, 3 * H_, H_, nullptr, 0);
    // W' = f16(Wih_ctx @ fc0_w)                   (1536 x 512 x 512)
    hgemm_nt<<<dim3(4, 12), 256, HG_SMEM>>>(
        wihc_h, 512, fc0wT_h, 512, wprime_h, 512, 512, nullptr, 5);

    // ---- recurrence: ONE persistent kernel, software grid barriers ----
    recurrence_kernel<<<128, 256, RC_SMEM>>>(
        wcat_h, bcat, keys_h, att_v, feat_h,
        wprime_h, bias2, gix, qgh, ctx_h, gi, h, h16);

    // ---- logits: 2-stage HMMA, 2 CTA/SM (1920 x 32000 x 512) ----
    hgemm_nt2<<<dim3(V_ / 128, TOUT * B_ / 128), 256, HG2_SMEM>>>(
        h16 + B_ * H_, H_, fc2w_h, H_, out, V_, H_, fc2_b, 3);
}